// round 14
// baseline (speedup 1.0000x reference)
#include <cuda_runtime.h>
#include <cuda_fp16.h>
#include <math.h>

#define LL 2048
#define NN 4096
#define OO 128
#define NOUT 4224
#define FTVAL 0.2f

typedef unsigned long long ull;

// ---------------- scratch ----------------
static __device__ float g_aggK[(size_t)2 * NN * 64];
static __device__ float g_aggS[(size_t)2 * NN * 64];
static __device__ float g_gateK[2 * NN];
static __device__ float g_gateS[2 * NN];
static __device__ float g_Wx[64 * 128];     // [Wwk | Wws]
static __device__ float g_Wfu[192 * 128];   // [WfR | WuR]
static __device__ float g_Wb2[128 * 128];   // [Wf2 | Wout(pad)]
static __device__ float g_cF[2 * 64];
static __device__ float g_cU[2 * 64];
static __device__ unsigned g_bits[2 * OO * 128];
static __device__ unsigned g_h0[2 * LL * 32];   // w0 as half2, [row][lane]
static __device__ unsigned g_h1[2 * LL * 32];   // w1 as half2

// ---------------- helpers ----------------
__device__ __forceinline__ ull dup2(float a) {
    ull d; asm("mov.b64 %0, {%1, %1};" : "=l"(d) : "f"(a)); return d;
}
__device__ __forceinline__ void ffma2(ull &c, ull a, ull b) {
    asm("fma.rn.f32x2 %0, %1, %2, %3;" : "=l"(c) : "l"(a), "l"(b), "l"(c));
}
__device__ __forceinline__ float2 up2(ull v) {
    float2 f; asm("mov.b64 {%0, %1}, %2;" : "=f"(f.x), "=f"(f.y) : "l"(v)); return f;
}
__device__ __forceinline__ float sigm(float x) { return 1.f / (1.f + __expf(-x)); }

// exclusive warp scan; returns exclusive prefix, sets total
__device__ __forceinline__ int wscan_excl(int v, int lane, int &total) {
    int x = v;
#pragma unroll
    for (int d = 1; d < 32; d <<= 1) {
        int y = __shfl_up_sync(0xffffffffu, x, d);
        if (lane >= d) x += y;
    }
    total = __shfl_sync(0xffffffffu, x, 31);
    return x - v;
}

__device__ __forceinline__ unsigned mask8(const float4* src, int lane) {
    float4 v[8];
#pragma unroll
    for (int u = 0; u < 8; u++) v[u] = src[(size_t)u * 32 + lane];
    unsigned m = 0;
#pragma unroll
    for (int u = 0; u < 8; u++) {
        m |= (v[u].x != 0.f ? 1u : 0u) << (4 * u);
        m |= (v[u].y != 0.f ? 1u : 0u) << (4 * u + 1);
        m |= (v[u].z != 0.f ? 1u : 0u) << (4 * u + 2);
        m |= (v[u].w != 0.f ? 1u : 0u) << (4 * u + 3);
    }
    return m;
}

// ---------------- prep: w0/w1 -> half2 gather tables ----------------
__global__ void __launch_bounds__(256) k_prep(const float* __restrict__ w0,
                                              const float* __restrict__ w1) {
    int idx = blockIdx.x * 256 + threadIdx.x;   // 0..262143
    int i = idx & 131071;
    if (idx < 131072) {
        float2 v = ((const float2*)w0)[i];
        __half2 h = __floats2half2_rn(v.x, v.y);
        g_h0[i] = *(unsigned*)&h;
    } else {
        float2 v = ((const float2*)w1)[i];
        __half2 h = __floats2half2_rn(v.x, v.y);
        g_h1[i] = *(unsigned*)&h;
    }
}

// ================= mega kernel: setup (193) + opbits (128) + agg (2048) =================
__global__ void __launch_bounds__(256) k_mega(
        const float* __restrict__ ww, const float* __restrict__ wem,
        const float* __restrict__ dp0, const float* __restrict__ dp1,
        const float* __restrict__ w0, const float* __restrict__ w1,
        const float* __restrict__ wes, const float* __restrict__ wop,
        const float* __restrict__ Wf, const float* __restrict__ Wupd,
        const float* __restrict__ Wf2, const float* __restrict__ Wout,
        const float* __restrict__ Wwk, const float* __restrict__ Wws,
        const float* __restrict__ nh, const float* __restrict__ Wg,
        const float* __restrict__ bg) {
    int blk = blockIdx.x;
    int tid = threadIdx.x;

    if (blk < 193) {
        int half = tid >> 7, c = tid & 127;
        int ob = blk * 2 + half;   // 0..385
        if (ob < 192) {
            int k = ob;
            float v;
            if (c < 64) { int srcr = (k < 64) ? k : k + 64; v = Wf[srcr * 64 + c]; }
            else v = (k >= 64) ? Wupd[k * 64 + (c - 64)] : 0.f;
            g_Wfu[k * 128 + c] = v;
        } else if (ob < 320) {
            int k = ob - 192;
            float v;
            if (c < 64) v = Wf2[k * 64 + c];
            else v = (k >= 64) ? Wout[(k - 64) * 64 + (c - 64)] : 0.f;
            g_Wb2[k * 128 + c] = v;
        } else if (ob < 384) {
            int k = ob - 320;
            g_Wx[k * 128 + c] = (c < 64) ? Wwk[k * 64 + c] : Wws[k * 64 + (c - 64)];
        } else {
            int b = half;
            __shared__ float gt[2][64], red[2][64], gtn[2][64];
            int d = c;
            if (d < 64) {
                float acc = bg[d];
                for (int k = 0; k < 64; k++) acc += nh[b * 64 + k] * Wg[k * 64 + d];
                gt[half][d] = acc; red[half][d] = acc * acc;
            }
            __syncthreads();
            if (d == 0) { float s = 0.f; for (int k = 0; k < 64; k++) s += red[half][k]; red[half][0] = s; }
            __syncthreads();
            float nrm = sqrtf(red[half][0]);
            if (d < 64) gtn[half][d] = gt[half][d] / (nrm + 1e-30f);
            __syncthreads();
            if (d < 64) {
                float cf = 0.f, cu = 0.f;
                for (int h = 0; h < 64; h++) {
                    float v = gtn[half][h];
                    cf += v * Wf[(64 + h) * 64 + d];
                    cu += v * Wupd[h * 64 + d];
                }
                g_cF[b * 64 + d] = cf;
                g_cU[b * 64 + d] = cu;
            }
        }
        return;
    }
    if (blk < 321) {
        int w = ((blk - 193) * 256 + tid) >> 5;
        int lane = tid & 31;
        int b = w >> 9;
        int rem = w & 511;
        int og = rem >> 7, ng = rem & 127;
        int o = og * 32 + lane;
        const float* wesb = wes + b * NN;
        unsigned word = 0;
        for (int i2 = 0; i2 < 32; i2++) {
            int n = ng * 32 + i2;
            float v = wop[((size_t)(b * NN + n)) * OO + o];
            float s = wesb[n];
            word |= ((v != 0.f && s != 0.f) ? 1u : 0u) << i2;
        }
        g_bits[((b * OO + o) << 7) + ng] = word;
        return;
    }

    // ---- sparse aggregations ----
    __shared__ int buf[8][256];
    int wip = tid >> 5, lane = tid & 31;
    unsigned ltm = (1u << lane) - 1u;
    int* B = buf[wip];
    int ablk = blk - 321;

    if (ablk < 1024) {
        // ---- word_w_k: scan ww, filter by wem, gather half2 rows ----
        int row = ablk * 8 + wip;
        int b = row >> 12;
        const float4* wwr = (const float4*)(ww + (size_t)row * NN);
        const float* wemr = wem + (size_t)row * NN;
        const unsigned* h0b = g_h0 + (size_t)b * LL * 32;
        const unsigned* h1b = g_h1 + (size_t)b * LL * 32;
        int cnt = 0;
#pragma unroll
        for (int half = 0; half < 2; half++) {
            unsigned ma = mask8(wwr + (size_t)(half * 16) * 32, lane);
            unsigned mb = mask8(wwr + (size_t)(half * 16 + 8) * 32, lane);
            int total;
            int off = wscan_excl(__popc(ma) + __popc(mb), lane, total);
            int pos = cnt + off;
            while (ma) {
                int bs = __ffs(ma) - 1;
                ma &= ma - 1u;
                int j = (half * 16 + (bs >> 2)) * 128 + lane * 4 + (bs & 3);
                if (pos < 256) B[pos] = j;
                pos++;
            }
            while (mb) {
                int bs = __ffs(mb) - 1;
                mb &= mb - 1u;
                int j = (half * 16 + 8 + (bs >> 2)) * 128 + lane * 4 + (bs & 3);
                if (pos < 256) B[pos] = j;
                pos++;
            }
            cnt += total;
        }
        if (cnt > 256) cnt = 256;
        __syncwarp();
        // filter by wem (lane-parallel gathers, re-compact)
        int cnt2 = 0;
        for (int base = 0; base < cnt; base += 32) {
            int t = base + lane;
            int j = (t < cnt) ? B[t] : -1;
            bool val = (j >= 0) && (wemr[j] != 0.f);
            unsigned bal = __ballot_sync(0xffffffffu, val);
            __syncwarp();
            if (val) B[cnt2 + __popc(bal & ltm)] = j;
            cnt2 += __popc(bal);
        }
        __syncwarp();
        // gather (half2 per lane), 8-way unrolled
        float a0 = 0.f, a1 = 0.f, c0 = 0.f, c1 = 0.f;
        int t = 0;
        for (; t + 8 <= cnt2; t += 8) {
            const unsigned* p[8];
#pragma unroll
            for (int q = 0; q < 8; q++) {
                int j = B[t + q];
                p[q] = (j < LL) ? h0b + (size_t)j * 32 : h1b + (size_t)(j - LL) * 32;
            }
            unsigned gv[8];
#pragma unroll
            for (int q = 0; q < 8; q++) gv[q] = p[q][lane];
#pragma unroll
            for (int q = 0; q < 8; q++) {
                float2 g = __half22float2(*(const __half2*)&gv[q]);
                if (q & 1) { c0 += g.x; c1 += g.y; } else { a0 += g.x; a1 += g.y; }
            }
        }
        for (; t < cnt2; t++) {
            int j = B[t];
            const unsigned* p = (j < LL) ? h0b + (size_t)j * 32 : h1b + (size_t)(j - LL) * 32;
            unsigned gv = p[lane];
            float2 g = __half22float2(*(const __half2*)&gv);
            a0 += g.x; a1 += g.y;
        }
        a0 += c0; a1 += c1;
        float inv = 1.f / ((float)cnt2 + 1e-30f);
        // layout: lane holds cols 2l, 2l+1
        ((float2*)(g_aggK + (size_t)row * 64))[lane] = make_float2(a0 * inv, a1 * inv);
        if (lane == 0) g_gateK[row] = (cnt2 > 0) ? 1.f : 0.f;
    } else {
        // ---- word_w_s: scan depend, gather half2 rows ----
        int row = (ablk - 1024) * 8 + wip;
        int b = row >> 12;
        int i = row & (NN - 1);
        const float* mat;
        const unsigned* Xh;
        if (i < LL) {
            mat = dp0 + ((size_t)(b * LL + i)) * LL;
            Xh = g_h0 + (size_t)b * LL * 32;
        } else {
            mat = dp1 + ((size_t)(b * LL + i - LL)) * LL;
            Xh = g_h1 + (size_t)b * LL * 32;
        }
        const float4* m4 = (const float4*)mat;
        unsigned ma = mask8(m4, lane);
        unsigned mb = mask8(m4 + (size_t)8 * 32, lane);
        int total;
        int off = wscan_excl(__popc(ma) + __popc(mb), lane, total);
        int pos = off;
        while (ma) {
            int bs = __ffs(ma) - 1;
            ma &= ma - 1u;
            int j = (bs >> 2) * 128 + lane * 4 + (bs & 3);
            if (pos < 256) B[pos] = j;
            pos++;
        }
        while (mb) {
            int bs = __ffs(mb) - 1;
            mb &= mb - 1u;
            int j = (8 + (bs >> 2)) * 128 + lane * 4 + (bs & 3);
            if (pos < 256) B[pos] = j;
            pos++;
        }
        int cnt = (total > 256) ? 256 : total;
        __syncwarp();
        float a0 = 0.f, a1 = 0.f, c0 = 0.f, c1 = 0.f;
        int t = 0;
        for (; t + 8 <= cnt; t += 8) {
            unsigned gv[8];
#pragma unroll
            for (int q = 0; q < 8; q++) gv[q] = Xh[(size_t)B[t + q] * 32 + lane];
#pragma unroll
            for (int q = 0; q < 8; q++) {
                float2 g = __half22float2(*(const __half2*)&gv[q]);
                if (q & 1) { c0 += g.x; c1 += g.y; } else { a0 += g.x; a1 += g.y; }
            }
        }
        for (; t < cnt; t++) {
            unsigned gv = Xh[(size_t)B[t] * 32 + lane];
            float2 g = __half22float2(*(const __half2*)&gv);
            a0 += g.x; a1 += g.y;
        }
        a0 += c0; a1 += c1;
        float inv = 1.f / ((float)cnt + 1e-30f);
        ((float2*)(g_aggS + (size_t)row * 64))[lane] = make_float2(a0 * inv, a1 * inv);
        if (lane == 0) g_gateS[row] = (cnt > 0) ? 1.f : 0.f;
    }
}

// ================= fused mega-GEMM: 128 threads, 4 rows/thread =================
__global__ void __launch_bounds__(128) k_fu(const float* __restrict__ w0,
                                            const float* __restrict__ w1,
                                            const float* __restrict__ gw,
                                            const float* __restrict__ bwk,
                                            const float* __restrict__ bws,
                                            const float* __restrict__ bf,
                                            const float* __restrict__ bupd,
                                            float* __restrict__ out) {
    __shared__ float SM[2176 + 2176 + 6272];
    float* R1 = SM;            // aggK (A) / allw (B), stride 68
    float* R2 = SM + 2176;     // aggS (A), stride 68
    float* WREG = SM + 4352;   // weight chunk 16x128
    float* C2 = WREG + 2048;   // 32 x stride 132

    int tid = threadIdx.x;
    int tx = tid & 15, ty = tid >> 4;
    int r0 = blockIdx.x * 32;
    int b = r0 >> 12, i0 = r0 & (NN - 1);

    {
        int row = tid >> 2, colq = (tid & 3) * 16;
        const float* sK = g_aggK + (size_t)(r0 + row) * 64 + colq;
        const float* sS = g_aggS + (size_t)(r0 + row) * 64 + colq;
#pragma unroll
        for (int u = 0; u < 4; u++) {
            *(float4*)&R1[row * 68 + colq + u * 4] = *(const float4*)(sK + u * 4);
            *(float4*)&R2[row * 68 + colq + u * 4] = *(const float4*)(sS + u * 4);
        }
    }

    ull acc[4][4];
#pragma unroll
    for (int i = 0; i < 4; i++)
#pragma unroll
        for (int j = 0; j < 4; j++) acc[i][j] = 0ull;

    // ---- phase A: [aggK|aggS] @ [Wwk|Wws] ----
    for (int kt = 0; kt < 64; kt += 16) {
        __syncthreads();
        {
            int row = tid >> 3, col = (tid & 7) * 16;
#pragma unroll
            for (int u = 0; u < 4; u++)
                *(float4*)&WREG[row * 128 + col + u * 4] =
                    *(const float4*)(g_Wx + (kt + row) * 128 + col + u * 4);
        }
        __syncthreads();
#pragma unroll
        for (int k = 0; k < 16; k++) {
            ulonglong2 p0 = *(const ulonglong2*)&WREG[k * 128 + tx * 4];
            ulonglong2 p1 = *(const ulonglong2*)&WREG[k * 128 + 64 + tx * 4];
#pragma unroll
            for (int i = 0; i < 4; i++) {
                int r = ty * 4 + i;
                ull ak = dup2(R1[r * 68 + kt + k]);
                ull as = dup2(R2[r * 68 + kt + k]);
                ffma2(acc[i][0], ak, p0.x);
                ffma2(acc[i][1], ak, p0.y);
                ffma2(acc[i][2], as, p1.x);
                ffma2(acc[i][3], as, p1.y);
            }
        }
    }
#pragma unroll
    for (int i = 0; i < 4; i++) {
        int r = ty * 4 + i;
        float gk = g_gateK[r0 + r], gs = g_gateS[r0 + r];
        float wk[4], ws[4];
#pragma unroll
        for (int j = 0; j < 2; j++) {
            float2 pk = up2(acc[i][j]);
            float2 ps = up2(acc[i][2 + j]);
            int c = tx * 4 + 2 * j;
            wk[2 * j] = pk.x + gk * bwk[c];
            wk[2 * j + 1] = pk.y + gk * bwk[c + 1];
            ws[2 * j] = ps.x + gs * bws[c];
            ws[2 * j + 1] = ps.y + gs * bws[c + 1];
        }
        float sk = 0.f, ss = 0.f;
#pragma unroll
        for (int q = 0; q < 4; q++) { sk += wk[q] * wk[q]; ss += ws[q] * ws[q]; }
#pragma unroll
        for (int d = 8; d; d >>= 1) {
            sk += __shfl_xor_sync(0xffffffffu, sk, d);
            ss += __shfl_xor_sync(0xffffffffu, ss, d);
        }
        float ik = 1.f / (sqrtf(sk) + 1e-30f);
        float is = 1.f / (sqrtf(ss) + 1e-30f);
        *(float4*)&C2[r * 132 + tx * 4] =
            make_float4(wk[0] * ik, wk[1] * ik, wk[2] * ik, wk[3] * ik);
        *(float4*)&C2[r * 132 + 64 + tx * 4] =
            make_float4(ws[0] * is, ws[1] * is, ws[2] * is, ws[3] * is);
    }
    __syncthreads();
    {
        int row = tid >> 2, colq = (tid & 3) * 16;
        int i = i0 + row;
        const float* src = (i < LL) ? (w0 + ((size_t)(b * LL + i)) * 64)
                                    : (w1 + ((size_t)(b * LL + i - LL)) * 64);
#pragma unroll
        for (int u = 0; u < 4; u++)
            *(float4*)&R1[row * 68 + colq + u * 4] = *(const float4*)(src + colq + u * 4);
    }
#pragma unroll
    for (int i = 0; i < 4; i++)
#pragma unroll
        for (int j = 0; j < 4; j++) acc[i][j] = 0ull;

    // ---- phase B: [allw|wk|ws] @ Wfu ----
    for (int kt = 0; kt < 192; kt += 16) {
        __syncthreads();
        {
            int row = tid >> 3, col = (tid & 7) * 16;
#pragma unroll
            for (int u = 0; u < 4; u++)
                *(float4*)&WREG[row * 128 + col + u * 4] =
                    *(const float4*)(g_Wfu + (kt + row) * 128 + col + u * 4);
        }
        __syncthreads();
        const float* arow[4];
#pragma unroll
        for (int i = 0; i < 4; i++) {
            int r = ty * 4 + i;
            arow[i] = (kt < 64) ? &R1[r * 68 + kt] : &C2[r * 132 + kt - 64];
        }
#pragma unroll
        for (int k = 0; k < 16; k++) {
            ulonglong2 p0 = *(const ulonglong2*)&WREG[k * 128 + tx * 4];
            ulonglong2 p1 = *(const ulonglong2*)&WREG[k * 128 + 64 + tx * 4];
#pragma unroll
            for (int i = 0; i < 4; i++) {
                ull a = dup2(arow[i][k]);
                ffma2(acc[i][0], a, p0.x);
                ffma2(acc[i][1], a, p0.y);
                ffma2(acc[i][2], a, p1.x);
                ffma2(acc[i][3], a, p1.y);
            }
        }
    }
    __syncthreads();
#pragma unroll
    for (int i = 0; i < 4; i++) {
        int r = ty * 4 + i;
        int iw = i0 + r;
        float gate = (gw[b * NN + iw] > 0.f) ? 1.f : 0.f;
        float4 aw4 = *(const float4*)&R1[r * 68 + tx * 4];
        float aw[4] = {aw4.x, aw4.y, aw4.z, aw4.w};
        float o[4];
#pragma unroll
        for (int j = 0; j < 2; j++) {
            float2 pf = up2(acc[i][j]);
            float2 pu = up2(acc[i][2 + j]);
#pragma unroll
            for (int h = 0; h < 2; h++) {
                int c = tx * 4 + 2 * j + h;
                float fv = sigm((h ? pf.y : pf.x) + bf[c] + gate * g_cF[b * 64 + c]);
                float uv = fmaxf((h ? pu.y : pu.x) + bupd[c] + gate * g_cU[b * 64 + c], 0.f);
                o[2 * j + h] = fmaxf(fv, FTVAL) * aw[2 * j + h] + (1.f - fv) * uv;
            }
        }
        *(float4*)(out + ((size_t)(b * NOUT + iw)) * 64 + tx * 4) =
            make_float4(o[0], o[1], o[2], o[3]);
    }
}

// ================= fused op: aggregate upd + Wo matvec + Wb2 matvec + gates =================
__global__ void __launch_bounds__(256) k_op(const float* __restrict__ opE,
                                            const float* __restrict__ Wo,
                                            const float* __restrict__ bo,
                                            const float* __restrict__ bf2,
                                            const float* __restrict__ bout,
                                            float* __restrict__ out) {
    int rg = blockIdx.x;              // b*128 + o
    int b = rg >> 7, oo = rg & (OO - 1);
    int tid = threadIdx.x;
    __shared__ float part[4][65];
    __shared__ int sdeg[4];
    __shared__ float aggU[64];
    __shared__ float cat[128];        // [opE row | word_op row]
    __shared__ float v1[4][64];
    __shared__ float vsum[2][128];
    __shared__ float gdeg;

    // phase 1: aggregate word_updated rows (from out) by bitmask
    {
        int d = tid & 63, grp = tid >> 6;
        const float* Ub = out + ((size_t)b * NOUT) * 64;
        unsigned base = (unsigned)rg * 128;
        float a = 0.f;
        int cnt = 0;
        for (int wi = grp; wi < 128; wi += 4) {
            unsigned bits = g_bits[base + wi];
            cnt += __popc(bits);
            while (bits) {
                int j = wi * 32 + (__ffs(bits) - 1);
                bits &= bits - 1u;
                a += Ub[(size_t)j * 64 + d];
            }
        }
        part[grp][d] = a;
        if (d == 0) sdeg[grp] = cnt;
    }
    __syncthreads();
    if (tid < 64) {
        float s = part[0][tid] + part[1][tid] + part[2][tid] + part[3][tid];
        int deg = sdeg[0] + sdeg[1] + sdeg[2] + sdeg[3];
        aggU[tid] = s / ((float)deg + 1e-30f);
        cat[tid] = opE[(size_t)rg * 64 + tid];
        if (tid == 0) gdeg = (deg > 0) ? 1.f : 0.f;
    }
    __syncthreads();
    // phase 1.5: word_op = aggU @ Wo + gdeg*bo  (K split 4x16)
    {
        int c = tid & 63, q = tid >> 6;
        float s = 0.f;
        const float* Wp = Wo + (q * 16) * 64 + c;
        const float* ap = aggU + q * 16;
#pragma unroll
        for (int k = 0; k < 16; k++) s += ap[k] * Wp[k * 64];
        v1[q][c] = s;
    }
    __syncthreads();
    if (tid < 64)
        cat[64 + tid] = v1[0][tid] + v1[1][tid] + v1[2][tid] + v1[3][tid] + gdeg * bo[tid];
    __syncthreads();
    // phase 2: mat-vec  v[c] = sum_k cat[k] * Wb2[k][c], K split in halves
    {
        int half = tid >> 7, c = tid & 127;
        const float* Wb = g_Wb2 + (size_t)half * 64 * 128 + c;
        float a0 = 0.f, a1 = 0.f, a2 = 0.f, a3 = 0.f;
        const float* cp = cat + half * 64;
#pragma unroll
        for (int k = 0; k < 64; k += 4) {
            a0 += cp[k] * Wb[(size_t)k * 128];
            a1 += cp[k + 1] * Wb[(size_t)(k + 1) * 128];
            a2 += cp[k + 2] * Wb[(size_t)(k + 2) * 128];
            a3 += cp[k + 3] * Wb[(size_t)(k + 3) * 128];
        }
        vsum[half][c] = (a0 + a1) + (a2 + a3);
    }
    __syncthreads();
    // phase 3: gates + output
    if (tid < 64) {
        float pf = vsum[0][tid] + vsum[1][tid] + bf2[tid];
        float pu = vsum[0][64 + tid] + vsum[1][64 + tid] + bout[tid];
        float fv = sigm(pf);
        float uv = fmaxf(pu, 0.f);
        float e = cat[tid];
        out[((size_t)(b * NOUT + NN + oo)) * 64 + tid] =
            fmaxf(fv, FTVAL) * e + (1.f - fv) * uv;
    }
}

// ---------------- launch ----------------
extern "C" void kernel_launch(void* const* d_in, const int* in_sizes, int n_in,
                              void* d_out, int out_size) {
    (void)in_sizes; (void)n_in; (void)out_size;
    const float* w0   = (const float*)d_in[0];
    const float* w1   = (const float*)d_in[1];
    const float* nh   = (const float*)d_in[2];
    const float* opE  = (const float*)d_in[3];
    const float* wes  = (const float*)d_in[4];
    const float* wem  = (const float*)d_in[5];
    const float* wop  = (const float*)d_in[6];
    const float* ww   = (const float*)d_in[7];
    const float* dp0  = (const float*)d_in[8];
    const float* dp1  = (const float*)d_in[9];
    const float* gw   = (const float*)d_in[10];
    const float* Wg   = (const float*)d_in[11];
    const float* bg   = (const float*)d_in[12];
    const float* Wwk  = (const float*)d_in[13];
    const float* bwk  = (const float*)d_in[14];
    const float* Wws  = (const float*)d_in[15];
    const float* bws  = (const float*)d_in[16];
    const float* Wo   = (const float*)d_in[17];
    const float* bo   = (const float*)d_in[18];
    const float* Wupd = (const float*)d_in[19];
    const float* bupd = (const float*)d_in[20];
    const float* Wf   = (const float*)d_in[21];
    const float* bf   = (const float*)d_in[22];
    const float* Wf2  = (const float*)d_in[23];
    const float* bf2  = (const float*)d_in[24];
    const float* Wout = (const float*)d_in[25];
    const float* bout = (const float*)d_in[26];
    float* out = (float*)d_out;

    k_prep<<<1024, 256>>>(w0, w1);
    k_mega<<<2369, 256>>>(ww, wem, dp0, dp1, w0, w1, wes, wop,
                          Wf, Wupd, Wf2, Wout, Wwk, Wws, nh, Wg, bg);
    k_fu<<<256, 128>>>(w0, w1, gw, bwk, bws, bf, bupd, out);
    k_op<<<256, 256>>>(opE, Wo, bo, bf2, bout, out);
}

// round 15
// speedup vs baseline: 1.0943x; 1.0943x over previous
#include <cuda_runtime.h>
#include <math.h>

#define LL 2048
#define NN 4096
#define OO 128
#define NOUT 4224
#define FTVAL 0.2f

typedef unsigned long long ull;

// ---------------- scratch ----------------
static __device__ float g_aggK[(size_t)2 * NN * 64];
static __device__ float g_aggS[(size_t)2 * NN * 64];
static __device__ float g_gateK[2 * NN];
static __device__ float g_gateS[2 * NN];
static __device__ float g_Wx[64 * 128];     // [Wwk | Wws]
static __device__ float g_Wfu[192 * 128];   // [WfR | WuR]
static __device__ float g_Wb2[128 * 128];   // [Wf2 | Wout(pad)]
static __device__ float g_cF[2 * 64];
static __device__ float g_cU[2 * 64];
static __device__ unsigned g_bits[2 * OO * 128];

// ---------------- helpers ----------------
__device__ __forceinline__ ull dup2(float a) {
    ull d; asm("mov.b64 %0, {%1, %1};" : "=l"(d) : "f"(a)); return d;
}
__device__ __forceinline__ void ffma2(ull &c, ull a, ull b) {
    asm("fma.rn.f32x2 %0, %1, %2, %3;" : "=l"(c) : "l"(a), "l"(b), "l"(c));
}
__device__ __forceinline__ float2 up2(ull v) {
    float2 f; asm("mov.b64 {%0, %1}, %2;" : "=f"(f.x), "=f"(f.y) : "l"(v)); return f;
}
__device__ __forceinline__ float sigm(float x) { return 1.f / (1.f + __expf(-x)); }

// exclusive warp scan; returns exclusive prefix, sets total
__device__ __forceinline__ int wscan_excl(int v, int lane, int &total) {
    int x = v;
#pragma unroll
    for (int d = 1; d < 32; d <<= 1) {
        int y = __shfl_up_sync(0xffffffffu, x, d);
        if (lane >= d) x += y;
    }
    total = __shfl_sync(0xffffffffu, x, 31);
    return x - v;
}

__device__ __forceinline__ unsigned mask8(const float4* src, int lane) {
    float4 v[8];
#pragma unroll
    for (int u = 0; u < 8; u++) v[u] = src[(size_t)u * 32 + lane];
    unsigned m = 0;
#pragma unroll
    for (int u = 0; u < 8; u++) {
        m |= (v[u].x != 0.f ? 1u : 0u) << (4 * u);
        m |= (v[u].y != 0.f ? 1u : 0u) << (4 * u + 1);
        m |= (v[u].z != 0.f ? 1u : 0u) << (4 * u + 2);
        m |= (v[u].w != 0.f ? 1u : 0u) << (4 * u + 3);
    }
    return m;
}

// ================= mega kernel: setup (193) + opbits (128) + agg (2048) =================
__global__ void __launch_bounds__(256) k_mega(
        const float* __restrict__ ww, const float* __restrict__ wem,
        const float* __restrict__ dp0, const float* __restrict__ dp1,
        const float* __restrict__ w0, const float* __restrict__ w1,
        const float* __restrict__ wes, const float* __restrict__ wop,
        const float* __restrict__ Wf, const float* __restrict__ Wupd,
        const float* __restrict__ Wf2, const float* __restrict__ Wout,
        const float* __restrict__ Wwk, const float* __restrict__ Wws,
        const float* __restrict__ nh, const float* __restrict__ Wg,
        const float* __restrict__ bg) {
    int blk = blockIdx.x;
    int tid = threadIdx.x;

    if (blk < 193) {
        int half = tid >> 7, c = tid & 127;
        int ob = blk * 2 + half;   // 0..385
        if (ob < 192) {
            int k = ob;
            float v;
            if (c < 64) { int srcr = (k < 64) ? k : k + 64; v = Wf[srcr * 64 + c]; }
            else v = (k >= 64) ? Wupd[k * 64 + (c - 64)] : 0.f;
            g_Wfu[k * 128 + c] = v;
        } else if (ob < 320) {
            int k = ob - 192;
            float v;
            if (c < 64) v = Wf2[k * 64 + c];
            else v = (k >= 64) ? Wout[(k - 64) * 64 + (c - 64)] : 0.f;
            g_Wb2[k * 128 + c] = v;
        } else if (ob < 384) {
            int k = ob - 320;
            g_Wx[k * 128 + c] = (c < 64) ? Wwk[k * 64 + c] : Wws[k * 64 + (c - 64)];
        } else {
            int b = half;
            __shared__ float gt[2][64], red[2][64], gtn[2][64];
            int d = c;
            if (d < 64) {
                float acc = bg[d];
                for (int k = 0; k < 64; k++) acc += nh[b * 64 + k] * Wg[k * 64 + d];
                gt[half][d] = acc; red[half][d] = acc * acc;
            }
            __syncthreads();
            if (d == 0) { float s = 0.f; for (int k = 0; k < 64; k++) s += red[half][k]; red[half][0] = s; }
            __syncthreads();
            float nrm = sqrtf(red[half][0]);
            if (d < 64) gtn[half][d] = gt[half][d] / (nrm + 1e-30f);
            __syncthreads();
            if (d < 64) {
                float cf = 0.f, cu = 0.f;
                for (int h = 0; h < 64; h++) {
                    float v = gtn[half][h];
                    cf += v * Wf[(64 + h) * 64 + d];
                    cu += v * Wupd[h * 64 + d];
                }
                g_cF[b * 64 + d] = cf;
                g_cU[b * 64 + d] = cu;
            }
        }
        return;
    }
    if (blk < 321) {
        int w = ((blk - 193) * 256 + tid) >> 5;
        int lane = tid & 31;
        int b = w >> 9;
        int rem = w & 511;
        int og = rem >> 7, ng = rem & 127;
        int o = og * 32 + lane;
        const float* wesb = wes + b * NN;
        unsigned word = 0;
        for (int i2 = 0; i2 < 32; i2++) {
            int n = ng * 32 + i2;
            float v = wop[((size_t)(b * NN + n)) * OO + o];
            float s = wesb[n];
            word |= ((v != 0.f && s != 0.f) ? 1u : 0u) << i2;
        }
        g_bits[((b * OO + o) << 7) + ng] = word;
        return;
    }

    // ---- sparse aggregations ----
    __shared__ int buf[8][256];
    int wip = tid >> 5, lane = tid & 31;
    unsigned ltm = (1u << lane) - 1u;
    int* B = buf[wip];
    int ablk = blk - 321;

    if (ablk < 1024) {
        // ---- word_w_k: scan ww, filter by wem, gather float2 rows ----
        int row = ablk * 8 + wip;
        int b = row >> 12;
        const float4* wwr = (const float4*)(ww + (size_t)row * NN);
        const float* wemr = wem + (size_t)row * NN;
        const float* w0b = w0 + ((size_t)b * LL) * 64;
        const float* w1b = w1 + ((size_t)b * LL) * 64;
        int cnt = 0;
#pragma unroll
        for (int half = 0; half < 2; half++) {
            unsigned ma = mask8(wwr + (size_t)(half * 16) * 32, lane);
            unsigned mb = mask8(wwr + (size_t)(half * 16 + 8) * 32, lane);
            int total;
            int off = wscan_excl(__popc(ma) + __popc(mb), lane, total);
            int pos = cnt + off;
            while (ma) {
                int bs = __ffs(ma) - 1;
                ma &= ma - 1u;
                int j = (half * 16 + (bs >> 2)) * 128 + lane * 4 + (bs & 3);
                if (pos < 256) B[pos] = j;
                pos++;
            }
            while (mb) {
                int bs = __ffs(mb) - 1;
                mb &= mb - 1u;
                int j = (half * 16 + 8 + (bs >> 2)) * 128 + lane * 4 + (bs & 3);
                if (pos < 256) B[pos] = j;
                pos++;
            }
            cnt += total;
        }
        if (cnt > 256) cnt = 256;
        __syncwarp();
        // filter by wem (lane-parallel gathers, re-compact)
        int cnt2 = 0;
        for (int base = 0; base < cnt; base += 32) {
            int t = base + lane;
            int j = (t < cnt) ? B[t] : -1;
            bool val = (j >= 0) && (wemr[j] != 0.f);
            unsigned bal = __ballot_sync(0xffffffffu, val);
            __syncwarp();
            if (val) B[cnt2 + __popc(bal & ltm)] = j;
            cnt2 += __popc(bal);
        }
        __syncwarp();
        // gather (float2 per lane), 8-way unrolled
        float a0 = 0.f, a1 = 0.f, c0 = 0.f, c1 = 0.f;
        int t = 0;
        for (; t + 8 <= cnt2; t += 8) {
            const float2* p[8];
#pragma unroll
            for (int q = 0; q < 8; q++) {
                int j = B[t + q];
                p[q] = (const float2*)((j < LL) ? w0b + (size_t)j * 64
                                                : w1b + (size_t)(j - LL) * 64);
            }
            float2 g[8];
#pragma unroll
            for (int q = 0; q < 8; q++) g[q] = p[q][lane];
#pragma unroll
            for (int q = 0; q < 8; q++) {
                if (q & 1) { c0 += g[q].x; c1 += g[q].y; } else { a0 += g[q].x; a1 += g[q].y; }
            }
        }
        for (; t < cnt2; t++) {
            int j = B[t];
            const float2* p = (const float2*)((j < LL) ? w0b + (size_t)j * 64
                                                       : w1b + (size_t)(j - LL) * 64);
            float2 g = p[lane];
            a0 += g.x; a1 += g.y;
        }
        a0 += c0; a1 += c1;
        float inv = 1.f / ((float)cnt2 + 1e-30f);
        ((float2*)(g_aggK + (size_t)row * 64))[lane] = make_float2(a0 * inv, a1 * inv);
        if (lane == 0) g_gateK[row] = (cnt2 > 0) ? 1.f : 0.f;
    } else {
        // ---- word_w_s: scan depend, gather float2 rows ----
        int row = (ablk - 1024) * 8 + wip;
        int b = row >> 12;
        int i = row & (NN - 1);
        const float* mat;
        const float* Xb;
        if (i < LL) {
            mat = dp0 + ((size_t)(b * LL + i)) * LL;
            Xb = w0 + ((size_t)b * LL) * 64;
        } else {
            mat = dp1 + ((size_t)(b * LL + i - LL)) * LL;
            Xb = w1 + ((size_t)b * LL) * 64;
        }
        const float4* m4 = (const float4*)mat;
        unsigned ma = mask8(m4, lane);
        unsigned mb = mask8(m4 + (size_t)8 * 32, lane);
        int total;
        int off = wscan_excl(__popc(ma) + __popc(mb), lane, total);
        int pos = off;
        while (ma) {
            int bs = __ffs(ma) - 1;
            ma &= ma - 1u;
            int j = (bs >> 2) * 128 + lane * 4 + (bs & 3);
            if (pos < 256) B[pos] = j;
            pos++;
        }
        while (mb) {
            int bs = __ffs(mb) - 1;
            mb &= mb - 1u;
            int j = (8 + (bs >> 2)) * 128 + lane * 4 + (bs & 3);
            if (pos < 256) B[pos] = j;
            pos++;
        }
        int cnt = (total > 256) ? 256 : total;
        __syncwarp();
        float a0 = 0.f, a1 = 0.f, c0 = 0.f, c1 = 0.f;
        int t = 0;
        for (; t + 8 <= cnt; t += 8) {
            const float2* p[8];
#pragma unroll
            for (int q = 0; q < 8; q++) p[q] = (const float2*)(Xb + (size_t)B[t + q] * 64);
            float2 g[8];
#pragma unroll
            for (int q = 0; q < 8; q++) g[q] = p[q][lane];
#pragma unroll
            for (int q = 0; q < 8; q++) {
                if (q & 1) { c0 += g[q].x; c1 += g[q].y; } else { a0 += g[q].x; a1 += g[q].y; }
            }
        }
        for (; t < cnt; t++) {
            float2 g = ((const float2*)(Xb + (size_t)B[t] * 64))[lane];
            a0 += g.x; a1 += g.y;
        }
        a0 += c0; a1 += c1;
        float inv = 1.f / ((float)cnt + 1e-30f);
        ((float2*)(g_aggS + (size_t)row * 64))[lane] = make_float2(a0 * inv, a1 * inv);
        if (lane == 0) g_gateS[row] = (cnt > 0) ? 1.f : 0.f;
    }
}

// ================= fused mega-GEMM: 128 threads, 4 rows/thread =================
__global__ void __launch_bounds__(128) k_fu(const float* __restrict__ w0,
                                            const float* __restrict__ w1,
                                            const float* __restrict__ gw,
                                            const float* __restrict__ bwk,
                                            const float* __restrict__ bws,
                                            const float* __restrict__ bf,
                                            const float* __restrict__ bupd,
                                            float* __restrict__ out) {
    __shared__ float SM[2176 + 2176 + 6272];
    float* R1 = SM;            // aggK (A) / allw (B), stride 68
    float* R2 = SM + 2176;     // aggS (A), stride 68
    float* WREG = SM + 4352;   // weight chunk 16x128
    float* C2 = WREG + 2048;   // 32 x stride 132

    int tid = threadIdx.x;
    int tx = tid & 15, ty = tid >> 4;
    int r0 = blockIdx.x * 32;
    int b = r0 >> 12, i0 = r0 & (NN - 1);

    {
        int row = tid >> 2, colq = (tid & 3) * 16;
        const float* sK = g_aggK + (size_t)(r0 + row) * 64 + colq;
        const float* sS = g_aggS + (size_t)(r0 + row) * 64 + colq;
#pragma unroll
        for (int u = 0; u < 4; u++) {
            *(float4*)&R1[row * 68 + colq + u * 4] = *(const float4*)(sK + u * 4);
            *(float4*)&R2[row * 68 + colq + u * 4] = *(const float4*)(sS + u * 4);
        }
    }

    ull acc[4][4];
#pragma unroll
    for (int i = 0; i < 4; i++)
#pragma unroll
        for (int j = 0; j < 4; j++) acc[i][j] = 0ull;

    // ---- phase A: [aggK|aggS] @ [Wwk|Wws] ----
    for (int kt = 0; kt < 64; kt += 16) {
        __syncthreads();
        {
            int row = tid >> 3, col = (tid & 7) * 16;
#pragma unroll
            for (int u = 0; u < 4; u++)
                *(float4*)&WREG[row * 128 + col + u * 4] =
                    *(const float4*)(g_Wx + (kt + row) * 128 + col + u * 4);
        }
        __syncthreads();
#pragma unroll
        for (int k = 0; k < 16; k++) {
            ulonglong2 p0 = *(const ulonglong2*)&WREG[k * 128 + tx * 4];
            ulonglong2 p1 = *(const ulonglong2*)&WREG[k * 128 + 64 + tx * 4];
#pragma unroll
            for (int i = 0; i < 4; i++) {
                int r = ty * 4 + i;
                ull ak = dup2(R1[r * 68 + kt + k]);
                ull as = dup2(R2[r * 68 + kt + k]);
                ffma2(acc[i][0], ak, p0.x);
                ffma2(acc[i][1], ak, p0.y);
                ffma2(acc[i][2], as, p1.x);
                ffma2(acc[i][3], as, p1.y);
            }
        }
    }
#pragma unroll
    for (int i = 0; i < 4; i++) {
        int r = ty * 4 + i;
        float gk = g_gateK[r0 + r], gs = g_gateS[r0 + r];
        float wk[4], ws[4];
#pragma unroll
        for (int j = 0; j < 2; j++) {
            float2 pk = up2(acc[i][j]);
            float2 ps = up2(acc[i][2 + j]);
            int c = tx * 4 + 2 * j;
            wk[2 * j] = pk.x + gk * bwk[c];
            wk[2 * j + 1] = pk.y + gk * bwk[c + 1];
            ws[2 * j] = ps.x + gs * bws[c];
            ws[2 * j + 1] = ps.y + gs * bws[c + 1];
        }
        float sk = 0.f, ss = 0.f;
#pragma unroll
        for (int q = 0; q < 4; q++) { sk += wk[q] * wk[q]; ss += ws[q] * ws[q]; }
#pragma unroll
        for (int d = 8; d; d >>= 1) {
            sk += __shfl_xor_sync(0xffffffffu, sk, d);
            ss += __shfl_xor_sync(0xffffffffu, ss, d);
        }
        float ik = 1.f / (sqrtf(sk) + 1e-30f);
        float is = 1.f / (sqrtf(ss) + 1e-30f);
        *(float4*)&C2[r * 132 + tx * 4] =
            make_float4(wk[0] * ik, wk[1] * ik, wk[2] * ik, wk[3] * ik);
        *(float4*)&C2[r * 132 + 64 + tx * 4] =
            make_float4(ws[0] * is, ws[1] * is, ws[2] * is, ws[3] * is);
    }
    __syncthreads();
    {
        int row = tid >> 2, colq = (tid & 3) * 16;
        int i = i0 + row;
        const float* src = (i < LL) ? (w0 + ((size_t)(b * LL + i)) * 64)
                                    : (w1 + ((size_t)(b * LL + i - LL)) * 64);
#pragma unroll
        for (int u = 0; u < 4; u++)
            *(float4*)&R1[row * 68 + colq + u * 4] = *(const float4*)(src + colq + u * 4);
    }
#pragma unroll
    for (int i = 0; i < 4; i++)
#pragma unroll
        for (int j = 0; j < 4; j++) acc[i][j] = 0ull;

    // ---- phase B: [allw|wk|ws] @ Wfu ----
    for (int kt = 0; kt < 192; kt += 16) {
        __syncthreads();
        {
            int row = tid >> 3, col = (tid & 7) * 16;
#pragma unroll
            for (int u = 0; u < 4; u++)
                *(float4*)&WREG[row * 128 + col + u * 4] =
                    *(const float4*)(g_Wfu + (kt + row) * 128 + col + u * 4);
        }
        __syncthreads();
        const float* arow[4];
#pragma unroll
        for (int i = 0; i < 4; i++) {
            int r = ty * 4 + i;
            arow[i] = (kt < 64) ? &R1[r * 68 + kt] : &C2[r * 132 + kt - 64];
        }
#pragma unroll
        for (int k = 0; k < 16; k++) {
            ulonglong2 p0 = *(const ulonglong2*)&WREG[k * 128 + tx * 4];
            ulonglong2 p1 = *(const ulonglong2*)&WREG[k * 128 + 64 + tx * 4];
#pragma unroll
            for (int i = 0; i < 4; i++) {
                ull a = dup2(arow[i][k]);
                ffma2(acc[i][0], a, p0.x);
                ffma2(acc[i][1], a, p0.y);
                ffma2(acc[i][2], a, p1.x);
                ffma2(acc[i][3], a, p1.y);
            }
        }
    }
    __syncthreads();
#pragma unroll
    for (int i = 0; i < 4; i++) {
        int r = ty * 4 + i;
        int iw = i0 + r;
        float gate = (gw[b * NN + iw] > 0.f) ? 1.f : 0.f;
        float4 aw4 = *(const float4*)&R1[r * 68 + tx * 4];
        float aw[4] = {aw4.x, aw4.y, aw4.z, aw4.w};
        float o[4];
#pragma unroll
        for (int j = 0; j < 2; j++) {
            float2 pf = up2(acc[i][j]);
            float2 pu = up2(acc[i][2 + j]);
#pragma unroll
            for (int h = 0; h < 2; h++) {
                int c = tx * 4 + 2 * j + h;
                float fv = sigm((h ? pf.y : pf.x) + bf[c] + gate * g_cF[b * 64 + c]);
                float uv = fmaxf((h ? pu.y : pu.x) + bupd[c] + gate * g_cU[b * 64 + c], 0.f);
                o[2 * j + h] = fmaxf(fv, FTVAL) * aw[2 * j + h] + (1.f - fv) * uv;
            }
        }
        *(float4*)(out + ((size_t)(b * NOUT + iw)) * 64 + tx * 4) =
            make_float4(o[0], o[1], o[2], o[3]);
    }
}

// ================= fused op: decode bits -> index list, gather, matvecs, gates =================
__global__ void __launch_bounds__(256) k_op(const float* __restrict__ opE,
                                            const float* __restrict__ Wo,
                                            const float* __restrict__ bo,
                                            const float* __restrict__ bf2,
                                            const float* __restrict__ bout,
                                            float* __restrict__ out) {
    int rg = blockIdx.x;              // b*128 + o
    int b = rg >> 7, oo = rg & (OO - 1);
    int tid = threadIdx.x;
    __shared__ int idx[4096];
    __shared__ int s_cnt;
    __shared__ float part[4][65];
    __shared__ float aggU[64];
    __shared__ float cat[128];        // [opE row | word_op row]
    __shared__ float v1[4][64];
    __shared__ float vsum[2][128];
    __shared__ float gdeg;

    if (tid == 0) s_cnt = 0;
    __syncthreads();
    // phase 0: decode bits -> index list (threads 0..127 own one word each)
    if (tid < 128) {
        unsigned bits = g_bits[(unsigned)rg * 128 + tid];
        int n = __popc(bits);
        if (n) {
            int off = atomicAdd(&s_cnt, n);
            int base = tid * 32;
            while (bits) {
                int j = base + (__ffs(bits) - 1);
                bits &= bits - 1u;
                idx[off++] = j;
            }
        }
    }
    __syncthreads();
    int cnt = s_cnt;
    // phase 1: gather word_updated rows (from out), 4 groups x 4-deep unroll
    {
        int d = tid & 63, grp = tid >> 6;
        const float* Ub = out + ((size_t)b * NOUT) * 64;
        float a = 0.f;
        int t = grp;
        for (; t + 12 < cnt; t += 16) {
            int j0 = idx[t], j1 = idx[t + 4], j2 = idx[t + 8], j3 = idx[t + 12];
            float x0 = Ub[(size_t)j0 * 64 + d];
            float x1 = Ub[(size_t)j1 * 64 + d];
            float x2 = Ub[(size_t)j2 * 64 + d];
            float x3 = Ub[(size_t)j3 * 64 + d];
            a += (x0 + x1) + (x2 + x3);
        }
        for (; t < cnt; t += 4) a += Ub[(size_t)idx[t] * 64 + d];
        part[grp][d] = a;
    }
    __syncthreads();
    if (tid < 64) {
        float s = part[0][tid] + part[1][tid] + part[2][tid] + part[3][tid];
        aggU[tid] = s / ((float)cnt + 1e-30f);
        cat[tid] = opE[(size_t)rg * 64 + tid];
        if (tid == 0) gdeg = (cnt > 0) ? 1.f : 0.f;
    }
    __syncthreads();
    // phase 1.5: word_op = aggU @ Wo + gdeg*bo  (K split 4x16)
    {
        int c = tid & 63, q = tid >> 6;
        float s = 0.f;
        const float* Wp = Wo + (q * 16) * 64 + c;
        const float* ap = aggU + q * 16;
#pragma unroll
        for (int k = 0; k < 16; k++) s += ap[k] * Wp[k * 64];
        v1[q][c] = s;
    }
    __syncthreads();
    if (tid < 64)
        cat[64 + tid] = v1[0][tid] + v1[1][tid] + v1[2][tid] + v1[3][tid] + gdeg * bo[tid];
    __syncthreads();
    // phase 2: mat-vec  v[c] = sum_k cat[k] * Wb2[k][c], K split in halves
    {
        int half = tid >> 7, c = tid & 127;
        const float* Wb = g_Wb2 + (size_t)half * 64 * 128 + c;
        float a0 = 0.f, a1 = 0.f, a2 = 0.f, a3 = 0.f;
        const float* cp = cat + half * 64;
#pragma unroll
        for (int k = 0; k < 64; k += 4) {
            a0 += cp[k] * Wb[(size_t)k * 128];
            a1 += cp[k + 1] * Wb[(size_t)(k + 1) * 128];
            a2 += cp[k + 2] * Wb[(size_t)(k + 2) * 128];
            a3 += cp[k + 3] * Wb[(size_t)(k + 3) * 128];
        }
        vsum[half][c] = (a0 + a1) + (a2 + a3);
    }
    __syncthreads();
    // phase 3: gates + output
    if (tid < 64) {
        float pf = vsum[0][tid] + vsum[1][tid] + bf2[tid];
        float pu = vsum[0][64 + tid] + vsum[1][64 + tid] + bout[tid];
        float fv = sigm(pf);
        float uv = fmaxf(pu, 0.f);
        float e = cat[tid];
        out[((size_t)(b * NOUT + NN + oo)) * 64 + tid] =
            fmaxf(fv, FTVAL) * e + (1.f - fv) * uv;
    }
}

// ---------------- launch ----------------
extern "C" void kernel_launch(void* const* d_in, const int* in_sizes, int n_in,
                              void* d_out, int out_size) {
    (void)in_sizes; (void)n_in; (void)out_size;
    const float* w0   = (const float*)d_in[0];
    const float* w1   = (const float*)d_in[1];
    const float* nh   = (const float*)d_in[2];
    const float* opE  = (const float*)d_in[3];
    const float* wes  = (const float*)d_in[4];
    const float* wem  = (const float*)d_in[5];
    const float* wop  = (const float*)d_in[6];
    const float* ww   = (const float*)d_in[7];
    const float* dp0  = (const float*)d_in[8];
    const float* dp1  = (const float*)d_in[9];
    const float* gw   = (const float*)d_in[10];
    const float* Wg   = (const float*)d_in[11];
    const float* bg   = (const float*)d_in[12];
    const float* Wwk  = (const float*)d_in[13];
    const float* bwk  = (const float*)d_in[14];
    const float* Wws  = (const float*)d_in[15];
    const float* bws  = (const float*)d_in[16];
    const float* Wo   = (const float*)d_in[17];
    const float* bo   = (const float*)d_in[18];
    const float* Wupd = (const float*)d_in[19];
    const float* bupd = (const float*)d_in[20];
    const float* Wf   = (const float*)d_in[21];
    const float* bf   = (const float*)d_in[22];
    const float* Wf2  = (const float*)d_in[23];
    const float* bf2  = (const float*)d_in[24];
    const float* Wout = (const float*)d_in[25];
    const float* bout = (const float*)d_in[26];
    float* out = (float*)d_out;

    k_mega<<<2369, 256>>>(ww, wem, dp0, dp1, w0, w1, wes, wop,
                          Wf, Wupd, Wf2, Wout, Wwk, Wws, nh, Wg, bg);
    k_fu<<<256, 128>>>(w0, w1, gw, bwk, bws, bf, bupd, out);
    k_op<<<256, 256>>>(opE, Wo, bo, bf2, bout, out);
}